// round 6
// baseline (speedup 1.0000x reference)
#include <cuda_runtime.h>
#include <math_constants.h>

#define NB 4096
#define NC 1000
#define NT 9
#define RS 1024              /* smem row stride in floats */

#define LOG2E  1.4426950408889634f
#define LN2    0.6931471805599453f
#define C20K   0.07213475204444817f   /* 0.05 * log2(e) */
#define CTHR   0.7213475204444817f    /* 0.5  * log2(e) */

__device__ float g_A[NB];   // CE
__device__ float g_B[NB];   // (sum_t e_t * tgl_t * (KD_t - CE)) / sum_t e_t
__device__ float g_R[NB];   // row max over 8 teachers

__device__ __forceinline__ float ex2f(float x) {
    float r; asm("ex2.approx.ftz.f32 %0, %1;" : "=f"(r) : "f"(x)); return r;
}
__device__ __forceinline__ float lg2f(float x) {
    float r; asm("lg2.approx.ftz.f32 %0, %1;" : "=f"(r) : "f"(x)); return r;
}

__global__ __launch_bounds__(288, 3)
void mt_rows_kernel(const float* __restrict__ p0, const float* __restrict__ p1,
                    const float* __restrict__ p2, const float* __restrict__ p3,
                    const float* __restrict__ p4, const float* __restrict__ p5,
                    const float* __restrict__ p6, const float* __restrict__ p7,
                    const float* __restrict__ ps, const int* __restrict__ ptgt)
{
    const int b    = blockIdx.x;
    const int tid  = threadIdx.x;
    const int lane = tid & 31;
    const int wid  = tid >> 5;           // 0..8

    // Dtype probe: reference declares int64 targets; JAX-x64-off materializes int32.
    bool is64 = true;
#pragma unroll
    for (int k = 0; k < 16; k++) is64 = is64 && (ptgt[2 * k + 1] == 0);
    const int tgt = is64 ? ptgt[2 * b] : ptgt[b];

    const size_t row = (size_t)b * NC;

    __shared__ float srows[9 * RS];              // 8 teacher rows + student row
    __shared__ float pT1[8], pT2[8], pZ[8], pA[8];
    __shared__ float mM1[9], mM2[9], mZQ[9], mAQ[9];
    __shared__ float sZS1, sZS20;

    // per-warp source row
    const float* src;
    switch (wid) {
        case 0: src = p0; break; case 1: src = p1; break;
        case 2: src = p2; break; case 3: src = p3; break;
        case 4: src = p4; break; case 5: src = p5; break;
        case 6: src = p6; break; case 7: src = p7; break;
        default: src = ps; break;
    }
    float* myrow = srows + wid * RS;
    const bool isStudent = (wid == 8);

    // ---- phase 1: load row -> smem, per-lane top2 + Z (teachers) / zs (student)
    float4 ev[8];
    float t1 = -CUDART_INF_F, t2 = -CUDART_INF_F, Z = 0.f;
    float zs1 = 0.f, zs20 = 0.f;

#pragma unroll
    for (int k = 0; k < 8; k++) {
        const int idx = k * 128 + lane * 4;
        ev[k] = make_float4(0.f, 0.f, 0.f, 0.f);
        if (idx < NC) {
            const float4 v = *(const float4*)(src + row + idx);
            *(float4*)(myrow + idx) = v;
            if (!isStudent) {
                float4 e;
                e.x = ex2f(v.x * C20K); e.y = ex2f(v.y * C20K);
                e.z = ex2f(v.z * C20K); e.w = ex2f(v.w * C20K);
                Z += (e.x + e.y) + (e.z + e.w);
                ev[k] = e;
                // top-2 over 4 values
                {
                    float lo;
                    lo = fminf(t1, v.x); t1 = fmaxf(t1, v.x); t2 = fmaxf(t2, lo);
                    lo = fminf(t1, v.y); t1 = fmaxf(t1, v.y); t2 = fmaxf(t2, lo);
                    lo = fminf(t1, v.z); t1 = fmaxf(t1, v.z); t2 = fmaxf(t2, lo);
                    lo = fminf(t1, v.w); t1 = fmaxf(t1, v.w); t2 = fmaxf(t2, lo);
                }
            } else {
                zs1  += (ex2f(v.x * LOG2E) + ex2f(v.y * LOG2E))
                      + (ex2f(v.z * LOG2E) + ex2f(v.w * LOG2E));
                zs20 += (ex2f(v.x * C20K)  + ex2f(v.y * C20K))
                      + (ex2f(v.z * C20K)  + ex2f(v.w * C20K));
            }
        }
    }
    __syncthreads();

    // ---- phase 2a: teacher warps: A = sum e * s  (s from student smem row)
    float A = 0.f;
    if (!isStudent) {
#pragma unroll
        for (int k = 0; k < 8; k++) {
            const int idx = k * 128 + lane * 4;
            if (idx < NC) {
                const float4 s = *(const float4*)(srows + 8 * RS + idx);
                A = fmaf(ev[k].x, s.x, A);
                A = fmaf(ev[k].y, s.y, A);
                A = fmaf(ev[k].z, s.z, A);
                A = fmaf(ev[k].w, s.w, A);
            }
        }
        // warp-reduce t1,t2,Z,A
#pragma unroll
        for (int off = 16; off; off >>= 1) {
            const float o1 = __shfl_xor_sync(0xffffffffu, t1, off);
            const float o2 = __shfl_xor_sync(0xffffffffu, t2, off);
            const float hi = fmaxf(t1, o1);
            const float lo = fminf(t1, o1);
            t1 = hi;
            t2 = fmaxf(lo, fmaxf(t2, o2));
            Z += __shfl_xor_sync(0xffffffffu, Z, off);
            A += __shfl_xor_sync(0xffffffffu, A, off);
        }
        if (lane == 0) { pT1[wid] = t1; pT2[wid] = t2; pZ[wid] = Z; pA[wid] = A; }
    } else {
#pragma unroll
        for (int off = 16; off; off >>= 1) {
            zs1  += __shfl_xor_sync(0xffffffffu, zs1, off);
            zs20 += __shfl_xor_sync(0xffffffffu, zs20, off);
        }
        if (lane == 0) { sZS1 = zs1; sZS20 = zs20; }
    }

    // ---- phase 2b: mimic stats, cooperative over threads 0..249
    float m1 = -CUDART_INF_F, m2 = -CUDART_INF_F, Zm = 0.f, Am = 0.f;
    if (tid < 250) {
        const int c = tid * 4;
        const float4 r0 = *(const float4*)(srows + 0 * RS + c);
        const float4 r1 = *(const float4*)(srows + 1 * RS + c);
        const float4 r2 = *(const float4*)(srows + 2 * RS + c);
        const float4 r3 = *(const float4*)(srows + 3 * RS + c);
        const float4 r4 = *(const float4*)(srows + 4 * RS + c);
        const float4 r5 = *(const float4*)(srows + 5 * RS + c);
        const float4 r6 = *(const float4*)(srows + 6 * RS + c);
        const float4 r7 = *(const float4*)(srows + 7 * RS + c);
        const float4 sv = *(const float4*)(srows + 8 * RS + c);
        float mm[4], ss[4] = {sv.x, sv.y, sv.z, sv.w};
        mm[0] = 0.125f * (((r0.x + r1.x) + (r2.x + r3.x)) + ((r4.x + r5.x) + (r6.x + r7.x)));
        mm[1] = 0.125f * (((r0.y + r1.y) + (r2.y + r3.y)) + ((r4.y + r5.y) + (r6.y + r7.y)));
        mm[2] = 0.125f * (((r0.z + r1.z) + (r2.z + r3.z)) + ((r4.z + r5.z) + (r6.z + r7.z)));
        mm[3] = 0.125f * (((r0.w + r1.w) + (r2.w + r3.w)) + ((r4.w + r5.w) + (r6.w + r7.w)));
#pragma unroll
        for (int j = 0; j < 4; j++) {
            const float v = mm[j];
            const float lo = fminf(m1, v);
            m1 = fmaxf(m1, v);
            m2 = fmaxf(lo, fmaxf(m2, v < m1 ? v : lo));   // (kept simple below)
        }
        // redo top2 cleanly (the line above could be wrong; do it straightforwardly)
        m1 = -CUDART_INF_F; m2 = -CUDART_INF_F;
#pragma unroll
        for (int j = 0; j < 4; j++) {
            const float v = mm[j];
            const float lo = fminf(m1, v);
            m1 = fmaxf(m1, v);
            m2 = fmaxf(m2, lo);
            const float e = ex2f(v * C20K);
            Zm += e;
            Am = fmaf(e, ss[j], Am);
        }
    }
#pragma unroll
    for (int off = 16; off; off >>= 1) {
        const float o1 = __shfl_xor_sync(0xffffffffu, m1, off);
        const float o2 = __shfl_xor_sync(0xffffffffu, m2, off);
        const float hi = fmaxf(m1, o1);
        const float lo = fminf(m1, o1);
        m1 = hi;
        m2 = fmaxf(lo, fmaxf(m2, o2));
        Zm += __shfl_xor_sync(0xffffffffu, Zm, off);
        Am += __shfl_xor_sync(0xffffffffu, Am, off);
    }
    if (lane == 0) { mM1[wid] = m1; mM2[wid] = m2; mZQ[wid] = Zm; mAQ[wid] = Am; }
    __syncthreads();

    // ---- epilogue: warp 0
    if (wid == 0) {
        // combine 9 mimic partials across lanes 0..8 (lanes 9..15 neutral)
        float q1 = (lane < 9) ? mM1[lane] : -CUDART_INF_F;
        float q2 = (lane < 9) ? mM2[lane] : -CUDART_INF_F;
        float qZ = (lane < 9) ? mZQ[lane] : 0.f;
        float qA = (lane < 9) ? mAQ[lane] : 0.f;
#pragma unroll
        for (int off = 8; off; off >>= 1) {
            const float o1 = __shfl_xor_sync(0xffffffffu, q1, off);
            const float o2 = __shfl_xor_sync(0xffffffffu, q2, off);
            const float hi = fmaxf(q1, o1);
            const float lo = fminf(q1, o1);
            q1 = hi;
            q2 = fmaxf(lo, fmaxf(q2, o2));
            qZ += __shfl_xor_sync(0xffffffffu, qZ, off);
            qA += __shfl_xor_sync(0xffffffffu, qA, off);
        }
        const float M1 = __shfl_sync(0xffffffffu, q1, 0);
        const float M2 = __shfl_sync(0xffffffffu, q2, 0);
        const float MZ = __shfl_sync(0xffffffffu, qZ, 0);
        const float MA = __shfl_sync(0xffffffffu, qA, 0);

        // target logits: teacher t from its smem row; mimic = mean of the 8
        float tgl = (lane < 8) ? srows[lane * RS + tgt] : 0.f;
        float tsum = tgl;
#pragma unroll
        for (int off = 4; off; off >>= 1)
            tsum += __shfl_xor_sync(0xffffffffu, tsum, off);
        const float mimtgt = __shfl_sync(0xffffffffu, tsum, 0) * 0.125f;

        const float s_tgt = srows[8 * RS + tgt];
        const float CE = lg2f(sZS1) * LN2 - s_tgt;
        const float lse20 = lg2f(sZS20) * LN2;

        float e = 0.f, contrib = 0.f, rmaxv = -CUDART_INF_F;
        if (lane < NT) {
            const float g1 = (lane < 8) ? pT1[lane] : M1;
            const float g2 = (lane < 8) ? pT2[lane] : M2;
            const float gZ = (lane < 8) ? pZ[lane]  : MZ;
            const float gA = (lane < 8) ? pA[lane]  : MA;
            const float tg = (lane < 8) ? tgl : mimtgt;
            const float kd = 400.f * lse20 - 20.f * (gA / gZ);
            const float margin = (tg == g1) ? (g1 - g2) : 0.f;
            e = ex2f(margin * CTHR);
            contrib = e * tg * (kd - CE);
            if (lane < 8) rmaxv = g1;
        }
        float se = e, nm = contrib, rm = rmaxv;
#pragma unroll
        for (int off = 8; off; off >>= 1) {
            se += __shfl_xor_sync(0xffffffffu, se, off);
            nm += __shfl_xor_sync(0xffffffffu, nm, off);
            rm = fmaxf(rm, __shfl_xor_sync(0xffffffffu, rm, off));
        }
        if (lane == 0) {
            g_A[b] = CE;
            g_B[b] = nm / se;
            g_R[b] = rm;
        }
    }
}

__global__ __launch_bounds__(1024)
void mt_final_kernel(float* __restrict__ dout)
{
    const int tid  = threadIdx.x;
    const int lane = tid & 31;
    const int wid  = tid >> 5;
    __shared__ float sA[32], sB[32], sR[32];

    float a = 0.f, bb = 0.f, r = -CUDART_INF_F;
#pragma unroll
    for (int k = 0; k < NB / 1024; k++) {
        const int i = tid + k * 1024;
        a  += g_A[i];
        bb += g_B[i];
        r = fmaxf(r, g_R[i]);
    }
#pragma unroll
    for (int off = 16; off; off >>= 1) {
        a  += __shfl_xor_sync(0xffffffffu, a, off);
        bb += __shfl_xor_sync(0xffffffffu, bb, off);
        r = fmaxf(r, __shfl_xor_sync(0xffffffffu, r, off));
    }
    if (lane == 0) { sA[wid] = a; sB[wid] = bb; sR[wid] = r; }
    __syncthreads();
    if (tid == 0) {
        float ta = 0.f, tb = 0.f, tr = -CUDART_INF_F;
#pragma unroll
        for (int w = 0; w < 32; w++) {
            ta += sA[w]; tb += sB[w]; tr = fmaxf(tr, sR[w]);
        }
        dout[0] = ta * (1.f / NB) + 0.8f * tb / (tr * NB);
    }
}

extern "C" void kernel_launch(void* const* d_in, const int* in_sizes, int n_in,
                              void* d_out, int out_size)
{
    (void)in_sizes; (void)n_in; (void)out_size;
    mt_rows_kernel<<<NB, 288>>>(
        (const float*)d_in[0], (const float*)d_in[1],
        (const float*)d_in[2], (const float*)d_in[3],
        (const float*)d_in[4], (const float*)d_in[5],
        (const float*)d_in[6], (const float*)d_in[7],
        (const float*)d_in[8], (const int*)d_in[9]);
    mt_final_kernel<<<1, 1024>>>((float*)d_out);
}

// round 7
// speedup vs baseline: 1.5375x; 1.5375x over previous
#include <cuda_runtime.h>
#include <math_constants.h>

#define NB 4096
#define NC 1000
#define NT 9

#define LOG2E  1.4426950408889634f
#define LN2    0.6931471805599453f
#define C20K   0.07213475204444817f   /* 0.05 * log2(e) */
#define CTHR   0.7213475204444817f    /* 0.5  * log2(e) */

__device__ float g_A[NB];   // CE
__device__ float g_B[NB];   // (sum_t e_t * tgl_t * (KD_t - CE)) / sum_t e_t
__device__ float g_R[NB];   // max over 8 teachers

__device__ __forceinline__ float ex2f(float x) {
    float r; asm("ex2.approx.ftz.f32 %0, %1;" : "=f"(r) : "f"(x)); return r;
}
__device__ __forceinline__ float lg2f(float x) {
    float r; asm("lg2.approx.ftz.f32 %0, %1;" : "=f"(r) : "f"(x)); return r;
}

__global__ __launch_bounds__(256, 3)
void mt_rows_kernel(const float* __restrict__ p0, const float* __restrict__ p1,
                    const float* __restrict__ p2, const float* __restrict__ p3,
                    const float* __restrict__ p4, const float* __restrict__ p5,
                    const float* __restrict__ p6, const float* __restrict__ p7,
                    const float* __restrict__ ps, const int* __restrict__ ptgt)
{
    const int b    = blockIdx.x;
    const int tid  = threadIdx.x;
    const int lane = tid & 31;
    const int wid  = tid >> 5;

    // Dtype probe: reference declares int64 targets; JAX-x64-off materializes int32.
    bool is64 = true;
#pragma unroll
    for (int k = 0; k < 16; k++) is64 = is64 && (ptgt[2 * k + 1] == 0);
    const int tgt = is64 ? ptgt[2 * b] : ptgt[b];

    const size_t row = (size_t)b * NC;

    __shared__ float sm[8][32];
    __shared__ float s_tl[NT];   // per-teacher (and mimic) target logit
    __shared__ float s_tls;      // student target logit

    // m[t] = max over columns EXCLUDING target column; Z,A = KD sums
    float m[NT], Z[NT], A[NT];
#pragma unroll
    for (int t = 0; t < NT; t++) { m[t] = -CUDART_INF_F; Z[t] = 0.f; A[t] = 0.f; }
    float zs1 = 0.f, zs20 = 0.f;

    if (tid < 250) {
        const int c0 = tid * 4;
        const float4 sq = *(const float4*)(ps + row + c0);
        const float sv[4] = {sq.x, sq.y, sq.z, sq.w};
        bool isT[4];
#pragma unroll
        for (int j = 0; j < 4; j++) {
            isT[j] = ((c0 + j) == tgt);
            zs1  += ex2f(sv[j] * LOG2E);
            zs20 += ex2f(sv[j] * C20K);
            if (isT[j]) s_tls = sv[j];
        }

        float msum[4] = {0.f, 0.f, 0.f, 0.f};
        const float* ptr[8] = {p0, p1, p2, p3, p4, p5, p6, p7};
#pragma unroll
        for (int t = 0; t < 8; t++) {
            const float4 q = *(const float4*)(ptr[t] + row + c0);
            const float v[4] = {q.x, q.y, q.z, q.w};
#pragma unroll
            for (int j = 0; j < 4; j++) {
                msum[j] += v[j];
                const float e = ex2f(v[j] * C20K);
                Z[t] += e;
                A[t] = fmaf(e, sv[j], A[t]);
                m[t] = fmaxf(m[t], isT[j] ? -CUDART_INF_F : v[j]);
                if (isT[j]) s_tl[t] = v[j];
            }
        }
        // mimic (t=8)
#pragma unroll
        for (int j = 0; j < 4; j++) {
            const float mim = msum[j] * 0.125f;
            const float e = ex2f(mim * C20K);
            Z[8] += e;
            A[8] = fmaf(e, sv[j], A[8]);
            m[8] = fmaxf(m[8], isT[j] ? -CUDART_INF_F : mim);
            if (isT[j]) s_tl[8] = mim;
        }
    }

    // intra-warp reduction: 29 variables
#pragma unroll
    for (int off = 16; off; off >>= 1) {
#pragma unroll
        for (int t = 0; t < NT; t++) {
            m[t] = fmaxf(m[t], __shfl_xor_sync(0xffffffffu, m[t], off));
            Z[t] += __shfl_xor_sync(0xffffffffu, Z[t], off);
            A[t] += __shfl_xor_sync(0xffffffffu, A[t], off);
        }
        zs1  += __shfl_xor_sync(0xffffffffu, zs1, off);
        zs20 += __shfl_xor_sync(0xffffffffu, zs20, off);
    }

    if (lane == 0) {
#pragma unroll
        for (int t = 0; t < NT; t++) {
            sm[wid][t]      = m[t];
            sm[wid][9 + t]  = Z[t];
            sm[wid][18 + t] = A[t];
        }
        sm[wid][27] = zs1;
        sm[wid][28] = zs20;
    }
    __syncthreads();

    // warp 0 epilogue: lanes 0..8 each own one teacher branch
    if (wid == 0) {
        float gm = -CUDART_INF_F, gZ = 0.f, gA = 0.f, gz1 = 0.f, gz20 = 0.f;
        const int t = (lane < NT) ? lane : 0;
#pragma unroll
        for (int w = 0; w < 8; w++) {
            gm = fmaxf(gm, sm[w][t]);
            gZ  += sm[w][9 + t];
            gA  += sm[w][18 + t];
            gz1 += sm[w][27];
            gz20 += sm[w][28];
        }
        const float CE = lg2f(gz1) * LN2 - s_tls;
        const float lse20 = lg2f(gz20) * LN2;

        float e = 0.f, contrib = 0.f, rmaxv = -CUDART_INF_F;
        if (lane < NT) {
            const float tgl = s_tl[lane];
            const float kd = 400.f * lse20 - 20.f * (gA / gZ);
            const float margin = fmaxf(0.f, tgl - gm);   // == top1-top2 iff tgt is argmax
            e = ex2f(margin * CTHR);
            contrib = e * tgl * (kd - CE);
            if (lane < 8) rmaxv = fmaxf(gm, tgl);        // true row max (mimic excluded)
        }
        float se = e, nm = contrib, rm = rmaxv;
#pragma unroll
        for (int off = 8; off; off >>= 1) {
            se += __shfl_xor_sync(0xffffffffu, se, off);
            nm += __shfl_xor_sync(0xffffffffu, nm, off);
            rm = fmaxf(rm, __shfl_xor_sync(0xffffffffu, rm, off));
        }
        if (lane == 0) {
            g_A[b] = CE;
            g_B[b] = nm / se;
            g_R[b] = rm;
        }
    }
}

__global__ __launch_bounds__(1024)
void mt_final_kernel(float* __restrict__ dout)
{
    const int tid  = threadIdx.x;
    const int lane = tid & 31;
    const int wid  = tid >> 5;
    __shared__ float sA[32], sB[32], sR[32];

    float a = 0.f, bb = 0.f, r = -CUDART_INF_F;
#pragma unroll
    for (int k = 0; k < NB / 1024; k++) {
        const int i = tid + k * 1024;
        a  += g_A[i];
        bb += g_B[i];
        r = fmaxf(r, g_R[i]);
    }
#pragma unroll
    for (int off = 16; off; off >>= 1) {
        a  += __shfl_xor_sync(0xffffffffu, a, off);
        bb += __shfl_xor_sync(0xffffffffu, bb, off);
        r = fmaxf(r, __shfl_xor_sync(0xffffffffu, r, off));
    }
    if (lane == 0) { sA[wid] = a; sB[wid] = bb; sR[wid] = r; }
    __syncthreads();
    if (tid == 0) {
        float ta = 0.f, tb = 0.f, tr = -CUDART_INF_F;
#pragma unroll
        for (int w = 0; w < 32; w++) {
            ta += sA[w]; tb += sB[w]; tr = fmaxf(tr, sR[w]);
        }
        dout[0] = ta * (1.f / NB) + 0.8f * tb / (tr * NB);
    }
}

extern "C" void kernel_launch(void* const* d_in, const int* in_sizes, int n_in,
                              void* d_out, int out_size)
{
    (void)in_sizes; (void)n_in; (void)out_size;
    mt_rows_kernel<<<NB, 256>>>(
        (const float*)d_in[0], (const float*)d_in[1],
        (const float*)d_in[2], (const float*)d_in[3],
        (const float*)d_in[4], (const float*)d_in[5],
        (const float*)d_in[6], (const float*)d_in[7],
        (const float*)d_in[8], (const int*)d_in[9]);
    mt_final_kernel<<<1, 1024>>>((float*)d_out);
}